// round 13
// baseline (speedup 1.0000x reference)
#include <cuda_runtime.h>
#include <cstdint>

#define D    128
#define OUTC 16
#define MAXN 50000

typedef unsigned long long ull;

__device__ float g_P[MAXN * 32];   // [n][0:16]=W_u.hn + b, [n][16:32]=W_v.hn
__device__ int   g_idx_stride;     // 1 = int32 indices, 2 = int64 (read low word)

__device__ __forceinline__ ull pack2(float v) {
    ull r;
    asm("mov.b64 %0, {%1, %1};" : "=l"(r) : "r"(__float_as_uint(v)));
    return r;
}
__device__ __forceinline__ ull f2fma(ull a, ull b, ull c) {
    ull d;
    asm("fma.rn.f32x2 %0, %1, %2, %3;" : "=l"(d) : "l"(a), "l"(b), "l"(c));
    return d;
}
__device__ __forceinline__ unsigned smem_u32(const void* p) {
    return (unsigned)__cvta_generic_to_shared(p);
}
__device__ __forceinline__ void cp16(unsigned s, const void* g) {
    asm volatile("cp.async.cg.shared.global [%0], [%1], 16;" :: "r"(s), "l"(g));
}
__device__ __forceinline__ void cp_commit() {
    asm volatile("cp.async.commit_group;");
}
template <int N>
__device__ __forceinline__ void cp_wait() {
    asm volatile("cp.async.wait_group %0;" :: "n"(N));
}

// ===========================================================================
// Node projection: P[n][m] = dot(hn[n], Wrow(m)) (+ b folded into m<16 half)
// (unchanged from the 113.5us kernel to isolate the edge-kernel delta)
// ===========================================================================
__global__ __launch_bounds__(256, 3) void node_proj_kernel(
        const float* __restrict__ hn, const float* __restrict__ W,
        const float* __restrict__ b, int N,
        const unsigned* __restrict__ srcw, const unsigned* __restrict__ dstw) {
    extern __shared__ float sm[];
    float* buf0 = sm;                        // [128 rows][36]
    float* buf1 = sm + 128 * 36;
    ull*   Wp   = (ull*)(sm + 2 * 128 * 36); // [128 k][16 pairs]

    int tid = threadIdx.x;

    if (blockIdx.x == 0 && tid == 0) {
        bool i64 = true;
        for (int i = 0; i < 32 && i64; i++) if (srcw[2 * i + 1] != 0u) i64 = false;
        for (int i = 0; i < 32 && i64; i++) if (dstw[2 * i + 1] != 0u) i64 = false;
        g_idx_stride = i64 ? 2 : 1;
    }

    int n0   = blockIdx.x * 128;
    int srow = tid >> 3, scol = tid & 7;
    int q    = tid & 3;
    int g    = tid >> 2;

    auto stage = [&](int p) {
        float* buf = (p & 1) ? buf1 : buf0;
        int ph = p & 3;
#pragma unroll
        for (int t = 0; t < 4; t++) {
            int r = srow + t * 32;
            int rg = n0 + r; if (rg >= N) rg = N - 1;
            cp16(smem_u32(buf + r * 36 + scol * 4),
                 hn + (size_t)rg * D + ph * 32 + scol * 4);
        }
        cp_commit();
    };

    stage(0);
    stage(1);

    for (int i = tid; i < 128 * 16; i += 256) {
        int k = i >> 4, pg = i & 15;
        float w0, w1;
        if (pg < 8) { w0 = W[(2 * pg) * 384 + k];            w1 = W[(2 * pg + 1) * 384 + k]; }
        else        { w0 = W[(2 * pg - 16) * 384 + 128 + k]; w1 = W[(2 * pg - 15) * 384 + 128 + k]; }
        float2 t = make_float2(w0, w1);
        Wp[i] = *(ull*)&t;
    }

    ull acc[2][4];
#pragma unroll
    for (int j = 0; j < 2; j++)
#pragma unroll
        for (int p = 0; p < 4; p++) acc[j][p] = 0ull;

#pragma unroll 1
    for (int p = 0; p < 4; p++) {
        if (p == 3) cp_wait<0>(); else cp_wait<1>();
        __syncthreads();
        const float* buf = (p & 1) ? buf1 : buf0;
        int k0 = p * 32;
#pragma unroll
        for (int kc = 0; kc < 8; kc++) {
            float4 h0 = *(const float4*)(buf + g * 36 + kc * 4);
            float4 h1 = *(const float4*)(buf + (g + 64) * 36 + kc * 4);
            float hv0[4] = {h0.x, h0.y, h0.z, h0.w};
            float hv1[4] = {h1.x, h1.y, h1.z, h1.w};
#pragma unroll
            for (int kk = 0; kk < 4; kk++) {
                const ull* wr = Wp + (size_t)(k0 + kc * 4 + kk) * 16 + q * 4;
                ulonglong2 a  = *(const ulonglong2*)wr;
                ulonglong2 bq = *(const ulonglong2*)(wr + 2);
                ull w0 = a.x, w1 = a.y, w2 = bq.x, w3 = bq.y;
                ull hA = pack2(hv0[kk]);
                ull hB = pack2(hv1[kk]);
                acc[0][0] = f2fma(hA, w0, acc[0][0]);
                acc[0][1] = f2fma(hA, w1, acc[0][1]);
                acc[0][2] = f2fma(hA, w2, acc[0][2]);
                acc[0][3] = f2fma(hA, w3, acc[0][3]);
                acc[1][0] = f2fma(hB, w0, acc[1][0]);
                acc[1][1] = f2fma(hB, w1, acc[1][1]);
                acc[1][2] = f2fma(hB, w2, acc[1][2]);
                acc[1][3] = f2fma(hB, w3, acc[1][3]);
            }
        }
        __syncthreads();
        if (p < 2) stage(p + 2);
    }

    if (q < 2) {
#pragma unroll
        for (int pp = 0; pp < 4; pp++) {
            float2 bb = *(const float2*)(b + 2 * (q * 4 + pp));
#pragma unroll
            for (int j = 0; j < 2; j++) {
                float2 a = *(float2*)&acc[j][pp];
                a.x += bb.x; a.y += bb.y;
                acc[j][pp] = *(ull*)&a;
            }
        }
    }

#pragma unroll
    for (int j = 0; j < 2; j++) {
        int n = n0 + g + 64 * j;
        if (n < N) {
            ull* po = (ull*)(g_P + (size_t)n * 32 + q * 8);
#pragma unroll
            for (int pp = 0; pp < 4; pp++) po[pp] = acc[j][pp];
        }
    }
}

// ===========================================================================
// Edge pass (persistent, WARP-AUTONOMOUS): out[e] = W_e.he[e] + P[src] + P[dst]
// Each warp owns 32 edges per 256-edge subtile and runs its own cp.async
// 3-stage ring (32 rows x 20-float stride, 2.5 KB/stage). NO __syncthreads
// in the main loop: per-thread cp_wait + __syncwarp only. Lane l stages row
// l; lanes compute rows g=lane>>1 and g+16 (conflict-free LDS.128 phases).
// Thread = 2 edges x 8 outputs (half = lane&1). Epilogue-batched P gather.
// ===========================================================================
__global__ __launch_bounds__(256, 3) void edge_kernel(
        const float* __restrict__ he,
        const unsigned* __restrict__ srcw,
        const unsigned* __restrict__ dstw,
        const float* __restrict__ W,
        float* __restrict__ out, int E) {
    extern __shared__ float sm[];
    // per-warp ring: 3 stages x 32 rows x 20 floats = 1920 floats/warp
    ull* Wp = (ull*)(sm + 8 * 1920);         // [128 k][8 pairs]

    int tid  = threadIdx.x;
    int bid  = blockIdx.x;
    int grid = gridDim.x;
    int wid  = tid >> 5, lane = tid & 31;

    float* wbuf = sm + wid * 1920;
    int half = lane & 1;
    int g    = lane >> 1;                    // warp-local edges g, g+16

    int nsub = (E + 255) >> 8;
    int nw   = (bid < nsub) ? ((nsub - bid + grid - 1) / grid) : 0;
    int nph  = nw * 8;

    auto stage = [&](int p) {
        int w = p >> 3, ph = p & 7;
        int eb = ((bid + w * grid) << 8) + wid * 32;
        float* buf = wbuf + (p % 3) * 640;
        int rg = eb + lane; if (rg >= E) rg = E - 1;
        const float* src = he + (size_t)rg * D + ph * 16;
        unsigned dst = smem_u32(buf + lane * 20);
#pragma unroll
        for (int c = 0; c < 4; c++) cp16(dst + c * 16, src + c * 4);
        cp_commit();
    };

    if (nph > 0) {
        stage(0);
        if (nph > 1) stage(1);
    }

    // shared W tile (one-time, block-cooperative)
    for (int i = tid; i < 128 * 8; i += 256) {
        int k = i >> 3, pg = i & 7;
        float2 t = make_float2(W[(2 * pg) * 384 + 256 + k],
                               W[(2 * pg + 1) * 384 + 256 + k]);
        Wp[i] = *(ull*)&t;
    }
    __syncthreads();          // only block-wide sync; Wp ready
    if (nph == 0) return;

    int stride = g_idx_stride;

    ull acc[2][4];
#pragma unroll
    for (int j = 0; j < 2; j++)
#pragma unroll
        for (int pp = 0; pp < 4; pp++) acc[j][pp] = 0ull;

    int s0 = 0, d0 = 0, s1 = 0, d1 = 0;

#pragma unroll 1
    for (int p = 0; p < nph; p++) {
        int ph = p & 7, w = p >> 3;
        int eb = ((bid + w * grid) << 8) + wid * 32;

        if (ph == 0) {
            int eA = eb + g;      if (eA >= E) eA = E - 1;
            int eB = eb + g + 16; if (eB >= E) eB = E - 1;
            s0 = (int)srcw[(size_t)eA * stride];
            d0 = (int)dstw[(size_t)eA * stride];
            s1 = (int)srcw[(size_t)eB * stride];
            d1 = (int)dstw[(size_t)eB * stride];
        }

        if (p == nph - 1) cp_wait<0>(); else cp_wait<1>();
        __syncwarp();
        if (p + 2 < nph) stage(p + 2);   // ring slot last read in iter p-1

        const float* buf = wbuf + (p % 3) * 640;
        int k0 = ph * 16;
#pragma unroll
        for (int kc = 0; kc < 4; kc++) {
            float4 h0 = *(const float4*)(buf + g * 20 + kc * 4);
            float4 h1 = *(const float4*)(buf + (g + 16) * 20 + kc * 4);
            float hv0[4] = {h0.x, h0.y, h0.z, h0.w};
            float hv1[4] = {h1.x, h1.y, h1.z, h1.w};
#pragma unroll
            for (int kk = 0; kk < 4; kk++) {
                const ull* wr = Wp + (size_t)(k0 + kc * 4 + kk) * 8 + half * 4;
                ulonglong2 a  = *(const ulonglong2*)wr;
                ulonglong2 bq = *(const ulonglong2*)(wr + 2);
                ull w0 = a.x, w1 = a.y, w2 = bq.x, w3 = bq.y;
                ull hA = pack2(hv0[kk]);
                ull hB = pack2(hv1[kk]);
                acc[0][0] = f2fma(hA, w0, acc[0][0]);
                acc[0][1] = f2fma(hA, w1, acc[0][1]);
                acc[0][2] = f2fma(hA, w2, acc[0][2]);
                acc[0][3] = f2fma(hA, w3, acc[0][3]);
                acc[1][0] = f2fma(hB, w0, acc[1][0]);
                acc[1][1] = f2fma(hB, w1, acc[1][1]);
                acc[1][2] = f2fma(hB, w2, acc[1][2]);
                acc[1][3] = f2fma(hB, w3, acc[1][3]);
            }
        }

        if (ph == 7) {
            // epilogue: batched P gather (MLP 8), add, store, reset acc
            const float4* puA = (const float4*)(g_P + (size_t)s0 * 32 + half * 8);
            const float4* pvA = (const float4*)(g_P + (size_t)d0 * 32 + 16 + half * 8);
            const float4* puB = (const float4*)(g_P + (size_t)s1 * 32 + half * 8);
            const float4* pvB = (const float4*)(g_P + (size_t)d1 * 32 + 16 + half * 8);
            float4 uA0 = puA[0], uA1 = puA[1], vA0 = pvA[0], vA1 = pvA[1];
            float4 uB0 = puB[0], uB1 = puB[1], vB0 = pvB[0], vB1 = pvB[1];
#pragma unroll
            for (int j = 0; j < 2; j++) {
                int e = eb + g + 16 * j;
                if (e < E) {
                    float4 u0 = j ? uB0 : uA0, u1 = j ? uB1 : uA1;
                    float4 v0 = j ? vB0 : vA0, v1 = j ? vB1 : vA1;
                    float2 a0 = *(float2*)&acc[j][0];
                    float2 a1 = *(float2*)&acc[j][1];
                    float2 a2 = *(float2*)&acc[j][2];
                    float2 a3 = *(float2*)&acc[j][3];
                    float4 r0, r1;
                    r0.x = a0.x + u0.x + v0.x;
                    r0.y = a0.y + u0.y + v0.y;
                    r0.z = a1.x + u0.z + v0.z;
                    r0.w = a1.y + u0.w + v0.w;
                    r1.x = a2.x + u1.x + v1.x;
                    r1.y = a2.y + u1.y + v1.y;
                    r1.z = a3.x + u1.z + v1.z;
                    r1.w = a3.y + u1.w + v1.w;
                    float4* op = (float4*)(out + (size_t)e * OUTC + half * 8);
                    op[0] = r0;
                    op[1] = r1;
                }
            }
#pragma unroll
            for (int j = 0; j < 2; j++)
#pragma unroll
                for (int pp = 0; pp < 4; pp++) acc[j][pp] = 0ull;
        }
    }
}

// ===========================================================================
extern "C" void kernel_launch(void* const* d_in, const int* in_sizes, int n_in,
                              void* d_out, int out_size) {
    const float*    hn   = (const float*)d_in[0];
    const float*    he   = (const float*)d_in[1];
    const unsigned* srcw = (const unsigned*)d_in[2];
    const unsigned* dstw = (const unsigned*)d_in[3];
    const float*    W    = (const float*)d_in[4];
    const float*    b    = (const float*)d_in[5];
    float*          out  = (float*)d_out;

    int N = in_sizes[0] / D;
    int E = in_sizes[1] / D;

    const int smem_node = 2 * 128 * 36 * 4 + 128 * 16 * 8;   // 53248 B
    const int smem_edge = 8 * 1920 * 4 + 128 * 8 * 8;        // 69632 B
    cudaFuncSetAttribute(node_proj_kernel,
                         cudaFuncAttributeMaxDynamicSharedMemorySize, smem_node);
    cudaFuncSetAttribute(edge_kernel,
                         cudaFuncAttributeMaxDynamicSharedMemorySize, smem_edge);

    node_proj_kernel<<<(N + 127) / 128, 256, smem_node>>>(hn, W, b, N, srcw, dstw);
    edge_kernel<<<444, 256, smem_edge>>>(he, srcw, dstw, W, out, E);
}

// round 14
// speedup vs baseline: 1.1419x; 1.1419x over previous
#include <cuda_runtime.h>
#include <cstdint>

#define D    128
#define OUTC 16
#define MAXN 50000

typedef unsigned long long ull;

__device__ float g_P[MAXN * 32];   // [n][0:16]=W_u.hn + b, [n][16:32]=W_v.hn
__device__ int   g_idx_stride;     // 1 = int32 indices, 2 = int64 (read low word)

__device__ __forceinline__ ull pack2(float v) {
    ull r;
    asm("mov.b64 %0, {%1, %1};" : "=l"(r) : "r"(__float_as_uint(v)));
    return r;
}
__device__ __forceinline__ ull f2fma(ull a, ull b, ull c) {
    ull d;
    asm("fma.rn.f32x2 %0, %1, %2, %3;" : "=l"(d) : "l"(a), "l"(b), "l"(c));
    return d;
}
__device__ __forceinline__ unsigned smem_u32(const void* p) {
    return (unsigned)__cvta_generic_to_shared(p);
}
__device__ __forceinline__ void cp16(unsigned s, const void* g) {
    asm volatile("cp.async.cg.shared.global [%0], [%1], 16;" :: "r"(s), "l"(g));
}
__device__ __forceinline__ void cp_commit() {
    asm volatile("cp.async.commit_group;");
}
template <int N>
__device__ __forceinline__ void cp_wait() {
    asm volatile("cp.async.wait_group %0;" :: "n"(N));
}

// ===========================================================================
// Node projection: P[n][m] = dot(hn[n], Wrow(m)) (+ b folded into m<16 half)
// (unchanged — proven; isolates the edge-kernel delta)
// ===========================================================================
__global__ __launch_bounds__(256, 3) void node_proj_kernel(
        const float* __restrict__ hn, const float* __restrict__ W,
        const float* __restrict__ b, int N,
        const unsigned* __restrict__ srcw, const unsigned* __restrict__ dstw) {
    extern __shared__ float sm[];
    float* buf0 = sm;                        // [128 rows][36]
    float* buf1 = sm + 128 * 36;
    ull*   Wp   = (ull*)(sm + 2 * 128 * 36); // [128 k][16 pairs]

    int tid = threadIdx.x;

    if (blockIdx.x == 0 && tid == 0) {
        bool i64 = true;
        for (int i = 0; i < 32 && i64; i++) if (srcw[2 * i + 1] != 0u) i64 = false;
        for (int i = 0; i < 32 && i64; i++) if (dstw[2 * i + 1] != 0u) i64 = false;
        g_idx_stride = i64 ? 2 : 1;
    }

    int n0   = blockIdx.x * 128;
    int srow = tid >> 3, scol = tid & 7;
    int q    = tid & 3;
    int g    = tid >> 2;

    auto stage = [&](int p) {
        float* buf = (p & 1) ? buf1 : buf0;
        int ph = p & 3;
#pragma unroll
        for (int t = 0; t < 4; t++) {
            int r = srow + t * 32;
            int rg = n0 + r; if (rg >= N) rg = N - 1;
            cp16(smem_u32(buf + r * 36 + scol * 4),
                 hn + (size_t)rg * D + ph * 32 + scol * 4);
        }
        cp_commit();
    };

    stage(0);
    stage(1);

    for (int i = tid; i < 128 * 16; i += 256) {
        int k = i >> 4, pg = i & 15;
        float w0, w1;
        if (pg < 8) { w0 = W[(2 * pg) * 384 + k];            w1 = W[(2 * pg + 1) * 384 + k]; }
        else        { w0 = W[(2 * pg - 16) * 384 + 128 + k]; w1 = W[(2 * pg - 15) * 384 + 128 + k]; }
        float2 t = make_float2(w0, w1);
        Wp[i] = *(ull*)&t;
    }

    ull acc[2][4];
#pragma unroll
    for (int j = 0; j < 2; j++)
#pragma unroll
        for (int p = 0; p < 4; p++) acc[j][p] = 0ull;

#pragma unroll 1
    for (int p = 0; p < 4; p++) {
        if (p == 3) cp_wait<0>(); else cp_wait<1>();
        __syncthreads();
        const float* buf = (p & 1) ? buf1 : buf0;
        int k0 = p * 32;
#pragma unroll
        for (int kc = 0; kc < 8; kc++) {
            float4 h0 = *(const float4*)(buf + g * 36 + kc * 4);
            float4 h1 = *(const float4*)(buf + (g + 64) * 36 + kc * 4);
            float hv0[4] = {h0.x, h0.y, h0.z, h0.w};
            float hv1[4] = {h1.x, h1.y, h1.z, h1.w};
#pragma unroll
            for (int kk = 0; kk < 4; kk++) {
                const ull* wr = Wp + (size_t)(k0 + kc * 4 + kk) * 16 + q * 4;
                ulonglong2 a  = *(const ulonglong2*)wr;
                ulonglong2 bq = *(const ulonglong2*)(wr + 2);
                ull w0 = a.x, w1 = a.y, w2 = bq.x, w3 = bq.y;
                ull hA = pack2(hv0[kk]);
                ull hB = pack2(hv1[kk]);
                acc[0][0] = f2fma(hA, w0, acc[0][0]);
                acc[0][1] = f2fma(hA, w1, acc[0][1]);
                acc[0][2] = f2fma(hA, w2, acc[0][2]);
                acc[0][3] = f2fma(hA, w3, acc[0][3]);
                acc[1][0] = f2fma(hB, w0, acc[1][0]);
                acc[1][1] = f2fma(hB, w1, acc[1][1]);
                acc[1][2] = f2fma(hB, w2, acc[1][2]);
                acc[1][3] = f2fma(hB, w3, acc[1][3]);
            }
        }
        __syncthreads();
        if (p < 2) stage(p + 2);
    }

    if (q < 2) {
#pragma unroll
        for (int pp = 0; pp < 4; pp++) {
            float2 bb = *(const float2*)(b + 2 * (q * 4 + pp));
#pragma unroll
            for (int j = 0; j < 2; j++) {
                float2 a = *(float2*)&acc[j][pp];
                a.x += bb.x; a.y += bb.y;
                acc[j][pp] = *(ull*)&a;
            }
        }
    }

#pragma unroll
    for (int j = 0; j < 2; j++) {
        int n = n0 + g + 64 * j;
        if (n < N) {
            ull* po = (ull*)(g_P + (size_t)n * 32 + q * 8);
#pragma unroll
            for (int pp = 0; pp < 4; pp++) po[pp] = acc[j][pp];
        }
    }
}

// ===========================================================================
// Edge pass (persistent, 2 CTAs/SM, 4 EDGES/THREAD):
//   out[e] = W_e.he[e] + P[src[e]] + P[dst[e]]
// Subtiles of 512 edges, 8 phases of 16 k, stride 20 floats (80 B, aligned,
// conflict-free). Double buffer, cp_wait<1> depth-2, proven R4 schedule
// (wait; bar; compute; bar; stage(p+2)). Thread = 4 edges x 8 outputs:
// each 32 B W fetch feeds 16 FFMA2 (W-LDS traffic halved vs 2-edge tiles).
// ===========================================================================
__global__ __launch_bounds__(256, 2) void edge_kernel(
        const float* __restrict__ he,
        const unsigned* __restrict__ srcw,
        const unsigned* __restrict__ dstw,
        const float* __restrict__ W,
        float* __restrict__ out, int E) {
    extern __shared__ float sm[];
    float* buf0 = sm;                        // [512 rows][20]
    float* buf1 = sm + 512 * 20;
    ull*   Wp   = (ull*)(sm + 2 * 512 * 20); // [128 k][8 pairs]

    int tid  = threadIdx.x;
    int bid  = blockIdx.x;
    int grid = gridDim.x;

    int srow = tid >> 2, scol = tid & 3;     // 4 cp16 segments per 16-k row
    int half = tid & 1;                      // outs [8*half, 8*half+8)
    int g    = tid >> 1;                     // edges eb+g+128j, j=0..3

    int nsub = (E + 511) >> 9;
    int nw   = (bid < nsub) ? ((nsub - bid + grid - 1) / grid) : 0;
    int nph  = nw * 8;
    if (nph == 0) return;

    auto stage = [&](int p) {
        int w = p >> 3, ph = p & 7;
        int eb = (bid + w * grid) << 9;
        float* buf = (p & 1) ? buf1 : buf0;
#pragma unroll
        for (int t = 0; t < 8; t++) {
            int r = srow + t * 64;
            int rg = eb + r; if (rg >= E) rg = E - 1;
            cp16(smem_u32(buf + r * 20 + scol * 4),
                 he + (size_t)rg * D + ph * 16 + scol * 4);
        }
        cp_commit();
    };

    stage(0);
    stage(1);

    for (int i = tid; i < 128 * 8; i += 256) {
        int k = i >> 3, pg = i & 7;
        float2 t = make_float2(W[(2 * pg) * 384 + 256 + k],
                               W[(2 * pg + 1) * 384 + 256 + k]);
        Wp[i] = *(ull*)&t;
    }

    int stride = g_idx_stride;

    ull acc[4][4];
#pragma unroll
    for (int j = 0; j < 4; j++)
#pragma unroll
        for (int pp = 0; pp < 4; pp++) acc[j][pp] = 0ull;

    int sidx[4], didx[4];

#pragma unroll 1
    for (int p = 0; p < nph; p++) {
        int ph = p & 7, w = p >> 3;
        int eb = (bid + w * grid) << 9;

        if (ph == 0) {
#pragma unroll
            for (int j = 0; j < 4; j++) {
                int e = eb + g + 128 * j; if (e >= E) e = E - 1;
                sidx[j] = (int)srcw[(size_t)e * stride];
                didx[j] = (int)dstw[(size_t)e * stride];
            }
        }

        if (p == nph - 1) cp_wait<0>(); else cp_wait<1>();
        __syncthreads();

        const float* buf = (p & 1) ? buf1 : buf0;
        int k0 = ph * 16;
#pragma unroll
        for (int kc = 0; kc < 4; kc++) {
            float4 h0 = *(const float4*)(buf + (g      ) * 20 + kc * 4);
            float4 h1 = *(const float4*)(buf + (g + 128) * 20 + kc * 4);
            float4 h2 = *(const float4*)(buf + (g + 256) * 20 + kc * 4);
            float4 h3 = *(const float4*)(buf + (g + 384) * 20 + kc * 4);
            float hv0[4] = {h0.x, h0.y, h0.z, h0.w};
            float hv1[4] = {h1.x, h1.y, h1.z, h1.w};
            float hv2[4] = {h2.x, h2.y, h2.z, h2.w};
            float hv3[4] = {h3.x, h3.y, h3.z, h3.w};
#pragma unroll
            for (int kk = 0; kk < 4; kk++) {
                const ull* wr = Wp + (size_t)(k0 + kc * 4 + kk) * 8 + half * 4;
                ulonglong2 a  = *(const ulonglong2*)wr;
                ulonglong2 bq = *(const ulonglong2*)(wr + 2);
                ull w0 = a.x, w1 = a.y, w2 = bq.x, w3 = bq.y;
                ull hA = pack2(hv0[kk]);
                ull hB = pack2(hv1[kk]);
                ull hC = pack2(hv2[kk]);
                ull hD = pack2(hv3[kk]);
                acc[0][0] = f2fma(hA, w0, acc[0][0]);
                acc[0][1] = f2fma(hA, w1, acc[0][1]);
                acc[0][2] = f2fma(hA, w2, acc[0][2]);
                acc[0][3] = f2fma(hA, w3, acc[0][3]);
                acc[1][0] = f2fma(hB, w0, acc[1][0]);
                acc[1][1] = f2fma(hB, w1, acc[1][1]);
                acc[1][2] = f2fma(hB, w2, acc[1][2]);
                acc[1][3] = f2fma(hB, w3, acc[1][3]);
                acc[2][0] = f2fma(hC, w0, acc[2][0]);
                acc[2][1] = f2fma(hC, w1, acc[2][1]);
                acc[2][2] = f2fma(hC, w2, acc[2][2]);
                acc[2][3] = f2fma(hC, w3, acc[2][3]);
                acc[3][0] = f2fma(hD, w0, acc[3][0]);
                acc[3][1] = f2fma(hD, w1, acc[3][1]);
                acc[3][2] = f2fma(hD, w2, acc[3][2]);
                acc[3][3] = f2fma(hD, w3, acc[3][3]);
            }
        }
        __syncthreads();

        if (p + 2 < nph) stage(p + 2);

        if (ph == 7) {
            // epilogue: direct P gather per edge (L2-resident), add, store
#pragma unroll
            for (int j = 0; j < 4; j++) {
                int e = eb + g + 128 * j;
                if (e >= E) continue;
                const float4* pu = (const float4*)(g_P + (size_t)sidx[j] * 32 + half * 8);
                const float4* pv = (const float4*)(g_P + (size_t)didx[j] * 32 + 16 + half * 8);
                float4 u0 = pu[0], u1 = pu[1];
                float4 v0 = pv[0], v1 = pv[1];
                float2 a0 = *(float2*)&acc[j][0];
                float2 a1 = *(float2*)&acc[j][1];
                float2 a2 = *(float2*)&acc[j][2];
                float2 a3 = *(float2*)&acc[j][3];
                float4 r0, r1;
                r0.x = a0.x + u0.x + v0.x;
                r0.y = a0.y + u0.y + v0.y;
                r0.z = a1.x + u0.z + v0.z;
                r0.w = a1.y + u0.w + v0.w;
                r1.x = a2.x + u1.x + v1.x;
                r1.y = a2.y + u1.y + v1.y;
                r1.z = a3.x + u1.z + v1.z;
                r1.w = a3.y + u1.w + v1.w;
                float4* op = (float4*)(out + (size_t)e * OUTC + half * 8);
                op[0] = r0;
                op[1] = r1;
            }
#pragma unroll
            for (int j = 0; j < 4; j++)
#pragma unroll
                for (int pp = 0; pp < 4; pp++) acc[j][pp] = 0ull;
        }
    }
}

// ===========================================================================
extern "C" void kernel_launch(void* const* d_in, const int* in_sizes, int n_in,
                              void* d_out, int out_size) {
    const float*    hn   = (const float*)d_in[0];
    const float*    he   = (const float*)d_in[1];
    const unsigned* srcw = (const unsigned*)d_in[2];
    const unsigned* dstw = (const unsigned*)d_in[3];
    const float*    W    = (const float*)d_in[4];
    const float*    b    = (const float*)d_in[5];
    float*          out  = (float*)d_out;

    int N = in_sizes[0] / D;
    int E = in_sizes[1] / D;

    const int smem_node = 2 * 128 * 36 * 4 + 128 * 16 * 8;   // 53248 B
    const int smem_edge = 2 * 512 * 20 * 4 + 128 * 8 * 8;    // 90112 B
    cudaFuncSetAttribute(node_proj_kernel,
                         cudaFuncAttributeMaxDynamicSharedMemorySize, smem_node);
    cudaFuncSetAttribute(edge_kernel,
                         cudaFuncAttributeMaxDynamicSharedMemorySize, smem_edge);

    node_proj_kernel<<<(N + 127) / 128, 256, smem_node>>>(hn, W, b, N, srcw, dstw);
    edge_kernel<<<296, 256, smem_edge>>>(he, srcw, dstw, W, out, E);
}

// round 15
// speedup vs baseline: 1.1659x; 1.0210x over previous
#include <cuda_runtime.h>
#include <cstdint>

#define D    128
#define OUTC 16
#define MAXN 50000

typedef unsigned long long ull;

__device__ float    g_P[MAXN * 32];  // [n][0:16]=W_u.hn + b, [n][16:32]=W_v.hn
__device__ unsigned g_ctr;           // monotonic grid-barrier counter (replay-safe)

__device__ __forceinline__ ull pack2(float v) {
    ull r;
    asm("mov.b64 %0, {%1, %1};" : "=l"(r) : "r"(__float_as_uint(v)));
    return r;
}
__device__ __forceinline__ ull f2fma(ull a, ull b, ull c) {
    ull d;
    asm("fma.rn.f32x2 %0, %1, %2, %3;" : "=l"(d) : "l"(a), "l"(b), "l"(c));
    return d;
}
__device__ __forceinline__ unsigned smem_u32(const void* p) {
    return (unsigned)__cvta_generic_to_shared(p);
}
__device__ __forceinline__ void cp16(unsigned s, const void* g) {
    asm volatile("cp.async.cg.shared.global [%0], [%1], 16;" :: "r"(s), "l"(g));
}
__device__ __forceinline__ void cp_commit() {
    asm volatile("cp.async.commit_group;");
}
template <int N>
__device__ __forceinline__ void cp_wait() {
    asm volatile("cp.async.wait_group %0;" :: "n"(N));
}

// ===========================================================================
// Fused persistent kernel, grid 296, 2 CTAs/SM.
// Part 1: node projection tiles (128 nodes each), P[n] = Wu.hn+b | Wv.hn.
// Arrive on monotonic counter. Part 2: proven edge core (512-edge subtiles,
// 8 phases of 16 k, depth-2 cp.async, 4 edges/thread). Warps spin-wait for
// the grid barrier only at their FIRST P-gather epilogue (node work hides
// behind ~8 phases of edge GEMM).
// ===========================================================================
__global__ __launch_bounds__(256, 2) void fused_kernel(
        const float* __restrict__ hn,
        const float* __restrict__ he,
        const unsigned* __restrict__ srcw,
        const unsigned* __restrict__ dstw,
        const float* __restrict__ W,
        const float* __restrict__ b,
        float* __restrict__ out, int N, int E) {
    extern __shared__ float sm[];
    __shared__ unsigned s_nonzero;
    __shared__ unsigned s_target;

    int tid  = threadIdx.x;
    int bid  = blockIdx.x;
    int grid = gridDim.x;

    if (tid == 0) s_nonzero = 0u;

    // ---- CTA-local index dtype probe (64 parallel LDGs, no global dep) ----
    if (tid < 64) {
        unsigned v = (tid < 32) ? srcw[2 * tid + 1] : dstw[2 * (tid - 32) + 1];
        if (v) atomicOr(&s_nonzero, 1u);
    }

    // ======================= Part 1: node projection =======================
    {
        float* buf0 = sm;                        // [128 rows][36]
        float* buf1 = sm + 128 * 36;
        ull*   Wp   = (ull*)(sm + 2 * 128 * 36); // [128 k][16 pairs]

        int srow = tid >> 3, scol = tid & 7;
        int q    = tid & 3;
        int g    = tid >> 2;

        int ntiles = (N + 127) >> 7;
        bool first = true;

        for (int t = bid; t < ntiles; t += grid) {
            int n0 = t << 7;

            auto stage = [&](int p) {
                float* buf = (p & 1) ? buf1 : buf0;
                int ph = p & 3;
#pragma unroll
                for (int tt = 0; tt < 4; tt++) {
                    int r = srow + tt * 32;
                    int rg = n0 + r; if (rg >= N) rg = N - 1;
                    cp16(smem_u32(buf + r * 36 + scol * 4),
                         hn + (size_t)rg * D + ph * 32 + scol * 4);
                }
                cp_commit();
            };

            stage(0);
            stage(1);

            if (first) {
                for (int i = tid; i < 128 * 16; i += 256) {
                    int k = i >> 4, pg = i & 15;
                    float w0, w1;
                    if (pg < 8) { w0 = W[(2 * pg) * 384 + k];            w1 = W[(2 * pg + 1) * 384 + k]; }
                    else        { w0 = W[(2 * pg - 16) * 384 + 128 + k]; w1 = W[(2 * pg - 15) * 384 + 128 + k]; }
                    float2 tt = make_float2(w0, w1);
                    Wp[i] = *(ull*)&tt;
                }
                first = false;
            }

            ull acc[2][4];
#pragma unroll
            for (int j = 0; j < 2; j++)
#pragma unroll
                for (int pp = 0; pp < 4; pp++) acc[j][pp] = 0ull;

#pragma unroll 1
            for (int p = 0; p < 4; p++) {
                if (p == 3) cp_wait<0>(); else cp_wait<1>();
                __syncthreads();
                const float* buf = (p & 1) ? buf1 : buf0;
                int k0 = p * 32;
#pragma unroll
                for (int kc = 0; kc < 8; kc++) {
                    float4 h0 = *(const float4*)(buf + g * 36 + kc * 4);
                    float4 h1 = *(const float4*)(buf + (g + 64) * 36 + kc * 4);
                    float hv0[4] = {h0.x, h0.y, h0.z, h0.w};
                    float hv1[4] = {h1.x, h1.y, h1.z, h1.w};
#pragma unroll
                    for (int kk = 0; kk < 4; kk++) {
                        const ull* wr = Wp + (size_t)(k0 + kc * 4 + kk) * 16 + q * 4;
                        ulonglong2 a  = *(const ulonglong2*)wr;
                        ulonglong2 bq = *(const ulonglong2*)(wr + 2);
                        ull w0 = a.x, w1 = a.y, w2 = bq.x, w3 = bq.y;
                        ull hA = pack2(hv0[kk]);
                        ull hB = pack2(hv1[kk]);
                        acc[0][0] = f2fma(hA, w0, acc[0][0]);
                        acc[0][1] = f2fma(hA, w1, acc[0][1]);
                        acc[0][2] = f2fma(hA, w2, acc[0][2]);
                        acc[0][3] = f2fma(hA, w3, acc[0][3]);
                        acc[1][0] = f2fma(hB, w0, acc[1][0]);
                        acc[1][1] = f2fma(hB, w1, acc[1][1]);
                        acc[1][2] = f2fma(hB, w2, acc[1][2]);
                        acc[1][3] = f2fma(hB, w3, acc[1][3]);
                    }
                }
                __syncthreads();
                if (p < 2) stage(p + 2);
            }

            if (q < 2) {
#pragma unroll
                for (int pp = 0; pp < 4; pp++) {
                    float2 bb = *(const float2*)(b + 2 * (q * 4 + pp));
#pragma unroll
                    for (int j = 0; j < 2; j++) {
                        float2 a = *(float2*)&acc[j][pp];
                        a.x += bb.x; a.y += bb.y;
                        acc[j][pp] = *(ull*)&a;
                    }
                }
            }
#pragma unroll
            for (int j = 0; j < 2; j++) {
                int n = n0 + g + 64 * j;
                if (n < N) {
                    ull* po = (ull*)(g_P + (size_t)n * 32 + q * 8);
#pragma unroll
                    for (int pp = 0; pp < 4; pp++) po[pp] = acc[j][pp];
                }
            }
        }
    }

    // ---- arrive on grid barrier (release P writes) ----
    __threadfence();
    __syncthreads();
    if (tid == 0) {
        unsigned ticket = atomicAdd(&g_ctr, 1u);
        s_target = (ticket / (unsigned)grid + 1u) * (unsigned)grid;
    }
    __syncthreads();                     // also frees node smem for edge reuse
    unsigned target = s_target;
    int stride = s_nonzero ? 1 : 2;

    // ========================= Part 2: edge pass ==========================
    {
        float* buf0 = sm;                        // [512 rows][20]
        float* buf1 = sm + 512 * 20;
        ull*   Wp   = (ull*)(sm + 2 * 512 * 20); // [128 k][8 pairs]

        int srow = tid >> 2, scol = tid & 3;
        int half = tid & 1;
        int g    = tid >> 1;

        int nsub = (E + 511) >> 9;
        int nw   = (bid < nsub) ? ((nsub - bid + grid - 1) / grid) : 0;
        int nph  = nw * 8;
        if (nph == 0) return;

        auto stage = [&](int p) {
            int w = p >> 3, ph = p & 7;
            int eb = (bid + w * grid) << 9;
            float* buf = (p & 1) ? buf1 : buf0;
#pragma unroll
            for (int t = 0; t < 8; t++) {
                int r = srow + t * 64;
                int rg = eb + r; if (rg >= E) rg = E - 1;
                cp16(smem_u32(buf + r * 20 + scol * 4),
                     he + (size_t)rg * D + ph * 16 + scol * 4);
            }
            cp_commit();
        };

        stage(0);
        stage(1);

        for (int i = tid; i < 128 * 8; i += 256) {
            int k = i >> 3, pg = i & 7;
            float2 t = make_float2(W[(2 * pg) * 384 + 256 + k],
                                   W[(2 * pg + 1) * 384 + 256 + k]);
            Wp[i] = *(ull*)&t;
        }

        ull acc[4][4];
#pragma unroll
        for (int j = 0; j < 4; j++)
#pragma unroll
            for (int pp = 0; pp < 4; pp++) acc[j][pp] = 0ull;

        int sidx[4], didx[4];
        bool p_ready = false;

#pragma unroll 1
        for (int p = 0; p < nph; p++) {
            int ph = p & 7, w = p >> 3;
            int eb = (bid + w * grid) << 9;

            if (ph == 0) {
#pragma unroll
                for (int j = 0; j < 4; j++) {
                    int e = eb + g + 128 * j; if (e >= E) e = E - 1;
                    sidx[j] = (int)srcw[(size_t)e * stride];
                    didx[j] = (int)dstw[(size_t)e * stride];
                }
            }

            if (p == nph - 1) cp_wait<0>(); else cp_wait<1>();
            __syncthreads();

            const float* buf = (p & 1) ? buf1 : buf0;
            int k0 = ph * 16;
#pragma unroll
            for (int kc = 0; kc < 4; kc++) {
                float4 h0 = *(const float4*)(buf + (g      ) * 20 + kc * 4);
                float4 h1 = *(const float4*)(buf + (g + 128) * 20 + kc * 4);
                float4 h2 = *(const float4*)(buf + (g + 256) * 20 + kc * 4);
                float4 h3 = *(const float4*)(buf + (g + 384) * 20 + kc * 4);
                float hv0[4] = {h0.x, h0.y, h0.z, h0.w};
                float hv1[4] = {h1.x, h1.y, h1.z, h1.w};
                float hv2[4] = {h2.x, h2.y, h2.z, h2.w};
                float hv3[4] = {h3.x, h3.y, h3.z, h3.w};
#pragma unroll
                for (int kk = 0; kk < 4; kk++) {
                    const ull* wr = Wp + (size_t)(k0 + kc * 4 + kk) * 8 + half * 4;
                    ulonglong2 a  = *(const ulonglong2*)wr;
                    ulonglong2 bq = *(const ulonglong2*)(wr + 2);
                    ull w0 = a.x, w1 = a.y, w2 = bq.x, w3 = bq.y;
                    ull hA = pack2(hv0[kk]);
                    ull hB = pack2(hv1[kk]);
                    ull hC = pack2(hv2[kk]);
                    ull hD = pack2(hv3[kk]);
                    acc[0][0] = f2fma(hA, w0, acc[0][0]);
                    acc[0][1] = f2fma(hA, w1, acc[0][1]);
                    acc[0][2] = f2fma(hA, w2, acc[0][2]);
                    acc[0][3] = f2fma(hA, w3, acc[0][3]);
                    acc[1][0] = f2fma(hB, w0, acc[1][0]);
                    acc[1][1] = f2fma(hB, w1, acc[1][1]);
                    acc[1][2] = f2fma(hB, w2, acc[1][2]);
                    acc[1][3] = f2fma(hB, w3, acc[1][3]);
                    acc[2][0] = f2fma(hC, w0, acc[2][0]);
                    acc[2][1] = f2fma(hC, w1, acc[2][1]);
                    acc[2][2] = f2fma(hC, w2, acc[2][2]);
                    acc[2][3] = f2fma(hC, w3, acc[2][3]);
                    acc[3][0] = f2fma(hD, w0, acc[3][0]);
                    acc[3][1] = f2fma(hD, w1, acc[3][1]);
                    acc[3][2] = f2fma(hD, w2, acc[3][2]);
                    acc[3][3] = f2fma(hD, w3, acc[3][3]);
                }
            }
            __syncthreads();

            if (p + 2 < nph) stage(p + 2);

            if (ph == 7) {
                // one-time grid-barrier wait before the first P gather
                if (!p_ready) {
                    if ((tid & 31) == 0) {
                        while (atomicAdd(&g_ctr, 0u) < target) __nanosleep(128);
                    }
                    __syncwarp();
                    __threadfence();     // invalidate L1D so P reads are fresh
                    p_ready = true;
                }
#pragma unroll
                for (int j = 0; j < 4; j++) {
                    int e = eb + g + 128 * j;
                    if (e >= E) continue;
                    const float4* pu = (const float4*)(g_P + (size_t)sidx[j] * 32 + half * 8);
                    const float4* pv = (const float4*)(g_P + (size_t)didx[j] * 32 + 16 + half * 8);
                    float4 u0 = pu[0], u1 = pu[1];
                    float4 v0 = pv[0], v1 = pv[1];
                    float2 a0 = *(float2*)&acc[j][0];
                    float2 a1 = *(float2*)&acc[j][1];
                    float2 a2 = *(float2*)&acc[j][2];
                    float2 a3 = *(float2*)&acc[j][3];
                    float4 r0, r1;
                    r0.x = a0.x + u0.x + v0.x;
                    r0.y = a0.y + u0.y + v0.y;
                    r0.z = a1.x + u0.z + v0.z;
                    r0.w = a1.y + u0.w + v0.w;
                    r1.x = a2.x + u1.x + v1.x;
                    r1.y = a2.y + u1.y + v1.y;
                    r1.z = a3.x + u1.z + v1.z;
                    r1.w = a3.y + u1.w + v1.w;
                    float4* op = (float4*)(out + (size_t)e * OUTC + half * 8);
                    op[0] = r0;
                    op[1] = r1;
                }
#pragma unroll
                for (int j = 0; j < 4; j++)
#pragma unroll
                    for (int pp = 0; pp < 4; pp++) acc[j][pp] = 0ull;
            }
        }
    }
}

// ===========================================================================
extern "C" void kernel_launch(void* const* d_in, const int* in_sizes, int n_in,
                              void* d_out, int out_size) {
    const float*    hn   = (const float*)d_in[0];
    const float*    he   = (const float*)d_in[1];
    const unsigned* srcw = (const unsigned*)d_in[2];
    const unsigned* dstw = (const unsigned*)d_in[3];
    const float*    W    = (const float*)d_in[4];
    const float*    b    = (const float*)d_in[5];
    float*          out  = (float*)d_out;

    int N = in_sizes[0] / D;
    int E = in_sizes[1] / D;

    const int smem = 2 * 512 * 20 * 4 + 128 * 8 * 8;   // 90112 B (edge layout, superset)
    cudaFuncSetAttribute(fused_kernel,
                         cudaFuncAttributeMaxDynamicSharedMemorySize, smem);

    fused_kernel<<<296, 256, smem>>>(hn, he, srcw, dstw, W, b, out, N, E);
}